// round 15
// baseline (speedup 1.0000x reference)
#include <cuda_runtime.h>
#include <cuda_fp16.h>
#include <cstdint>

#define NN 100000
#define NNP (NN + 1)
#define EE 3200000
#define ECAP (EE + 16 * NN + 64)   // padded CSR capacity
#define FC 32
#define FULLMASK 0xFFFFFFFFu

// ---------------- scratch (device globals; no allocation anywhere) ----------
__device__ int   g_is64;
__device__ int   g_deg[NN];
__device__ float g_dinv[NN];
__device__ int   g_indptr[NN + 1];
__device__ int   g_pos[NN];
__device__ int4  g_ccsr4[ECAP / 4];       // padded cols, 16-edge-aligned rows
__device__ int   g_partials[512];

__device__ float g_tx1all[24 * NN * 4];   // layer1 basis fp32, float4-padded
__device__ uint2 g_tx1h[24 * NNP];        // layer1 fp16x4 mirror (stride NNP, sentinel row)
__device__ float g_txs[11 * NN * FC + 8192];  // Tx_1..Tx_11 fp32
__device__ float  g_bufA[NN * FC + 8192];
__device__ float  g_bufB[NN * FC + 8192];
__device__ __half g_h16A[NNP * FC];       // fp16 mirrors, PRE-SCALED by dinv, sentinel row NN
__device__ __half g_h16B[NNP * FC];
__device__ __half g_h16C[NNP * FC];
__device__ __half g_h16D[NNP * FC];

__device__ __forceinline__ float* selbuf(int s) {
    return (s == 0) ? g_bufA : g_bufB;
}
__device__ __forceinline__ __half* sel16(int s) {
    switch (s) {
        case 0:  return g_h16A;
        case 1:  return g_h16B;
        case 2:  return g_h16C;
        default: return g_h16D;
    }
}

__device__ __forceinline__ float silu(float x) {
    return x / (1.f + __expf(-x));
}

__device__ __forceinline__ uint2 pack4h(float a, float b, float c, float d) {
    __half2 lo = __floats2half2_rn(a, b);
    __half2 hi = __floats2half2_rn(c, d);
    uint2 r;
    r.x = *reinterpret_cast<unsigned*>(&lo);
    r.y = *reinterpret_cast<unsigned*>(&hi);
    return r;
}

// ---------------- dtype detect + zero degrees (merged) -----------------------
__global__ void k_init(const int* __restrict__ ei32) {
    int i = blockIdx.x * blockDim.x + threadIdx.x;
    if (i < NN) g_deg[i] = 0;
    if (blockIdx.x == 0) {
        __shared__ int ok;
        if (threadIdx.x == 0) ok = 1;
        __syncthreads();
        if (ei32[2 * threadIdx.x + 1] != 0) ok = 0;
        __syncthreads();
        if (threadIdx.x == 0) g_is64 = ok;
    }
}

// ---------------- graph preprocessing ---------------------------------------
__device__ __forceinline__ void decode_edge(const void* eiv, int e, int& r, int& c) {
    if (g_is64) {
        const long long* ei = (const long long*)eiv;
        r = (int)ei[e];
        c = (int)ei[EE + e];
    } else {
        const int* ei = (const int*)eiv;
        r = ei[e];
        c = ei[EE + e];
    }
    if ((unsigned)r >= NN) r = 0;
    if ((unsigned)c >= NN) c = 0;
}

__global__ void k_edges(const void* __restrict__ eiv) {
    int e = blockIdx.x * blockDim.x + threadIdx.x;
    if (e >= EE) return;
    int r, c;
    decode_edge(eiv, e, r, c);
    if (r != c) atomicAdd(&g_deg[r], 1);
}

// chunked exclusive scan of PADDED degrees into g_indptr (chunk = 512)
__global__ void k_scan1() {
    __shared__ int s[512];
    int i = blockIdx.x * 512 + threadIdx.x;
    int v = (i < NN) ? ((g_deg[i] + 15) & ~15) : 0;
    s[threadIdx.x] = v;
    __syncthreads();
    for (int off = 1; off < 512; off <<= 1) {
        int t = 0;
        if (threadIdx.x >= off) t = s[threadIdx.x - off];
        __syncthreads();
        if (threadIdx.x >= off) s[threadIdx.x] += t;
        __syncthreads();
    }
    if (i < NN) g_indptr[i] = s[threadIdx.x] - v;
    if (threadIdx.x == 511) g_partials[blockIdx.x] = s[511];
}

__global__ void k_scan2(int nb) {
    __shared__ int s[512];
    int v = (threadIdx.x < nb) ? g_partials[threadIdx.x] : 0;
    s[threadIdx.x] = v;
    __syncthreads();
    for (int off = 1; off < 512; off <<= 1) {
        int t = 0;
        if (threadIdx.x >= off) t = s[threadIdx.x - off];
        __syncthreads();
        if (threadIdx.x >= off) s[threadIdx.x] += t;
        __syncthreads();
    }
    if (threadIdx.x < nb) g_partials[threadIdx.x] = s[threadIdx.x] - v;
    if (threadIdx.x == 511) g_indptr[NN] = s[511];
}

// scan finalize + dinv (merged)
__global__ void k_scan3() {
    int i = blockIdx.x * blockDim.x + threadIdx.x;
    if (i < NN) {
        int p = g_indptr[i] + g_partials[i >> 9];
        g_indptr[i] = p;
        g_pos[i] = p;
        int d = g_deg[i];
        g_dinv[i] = (d > 0) ? rsqrtf((float)d) : 0.f;
    }
}

// fill CSR (real edges via atomics) + sentinel padding + pad x + zero sentinels
__global__ void k_fillpad(const void* __restrict__ eiv, const float* __restrict__ x,
                          int blocksE) {
    int* ccsr = (int*)g_ccsr4;
    if ((int)blockIdx.x < blocksE) {
        int e = blockIdx.x * blockDim.x + threadIdx.x;
        if (e >= EE) return;
        int r, c;
        decode_edge(eiv, e, r, c);
        if (r != c) {
            int p = atomicAdd(&g_pos[r], 1);
            ccsr[p] = c;
        }
    } else {
        int i = (blockIdx.x - blocksE) * blockDim.x + threadIdx.x;
        if (i >= NN) return;
        // sentinel padding cols for this node (disjoint from real-edge region)
        int p0 = g_indptr[i] + g_deg[i];
        int p1 = g_indptr[i + 1];
        for (int p = p0; p < p1; p++) ccsr[p] = NN;
        // pad x into layer-1 slot 0
        float a = x[3 * i + 0];
        float b = x[3 * i + 1];
        float c = x[3 * i + 2];
        float4 t; t.x = a; t.y = b; t.z = c; t.w = 0.f;
        ((float4*)g_tx1all)[i] = t;
        float dv = g_dinv[i];
        g_tx1h[i] = pack4h(dv * a, dv * b, dv * c, 0.f);
        // zero sentinel rows: layer-1 mirror slots + F=32 mirrors
        if (i < 24) {
            uint2 z; z.x = 0u; z.y = 0u;
            g_tx1h[i * NNP + NN] = z;
        }
        if (i < 8) {
            uint2 z; z.x = 0u; z.y = 0u;
            ((uint2*)g_h16A)[NN * 8 + i] = z;
            ((uint2*)g_h16B)[NN * 8 + i] = z;
            ((uint2*)g_h16C)[NN * 8 + i] = z;
            ((uint2*)g_h16D)[NN * 8 + i] = z;
        }
    }
}

// ---------------- layer 1 (F=3, fp16x4 scaled gather), warp per node --------
__global__ void k_l1_spmv(int ksrc, int kdst, int ktx0) {
    int gw   = (blockIdx.x * blockDim.x + threadIdx.x) >> 5;
    int lane = threadIdx.x & 31;
    if (gw >= NN) return;
    const uint2* vh = g_tx1h + (size_t)ksrc * NNP;
    const int* ccsr = (const int*)g_ccsr4;
    int s = g_indptr[gw];
    int e = g_indptr[gw + 1];
    float ax = 0.f, ay = 0.f, az = 0.f;
    for (int base = s; base < e; base += 32) {
        int j = base + lane;
        if (j < e) {
            int c = __ldg(&ccsr[j]);       // sentinel rows are zero -> safe
            uint2 hv = __ldg(&vh[c]);
            float2 f01 = __half22float2(*reinterpret_cast<__half2*>(&hv.x));
            float2 f23 = __half22float2(*reinterpret_cast<__half2*>(&hv.y));
            ax += f01.x;
            ay += f01.y;
            az += f23.x;
        }
    }
#pragma unroll
    for (int off = 16; off; off >>= 1) {
        ax += __shfl_xor_sync(FULLMASK, ax, off);
        ay += __shfl_xor_sync(FULLMASK, ay, off);
        az += __shfl_xor_sync(FULLMASK, az, off);
    }
    if (lane == 0) {
        float nd = -g_dinv[gw];
        ax *= nd; ay *= nd; az *= nd;
        float4* all = (float4*)g_tx1all;
        if (ktx0 >= 0) {
            float4 t0 = all[(size_t)ktx0 * NN + gw];
            ax = 2.f * ax - t0.x;
            ay = 2.f * ay - t0.y;
            az = 2.f * az - t0.z;
        }
        float4 r; r.x = ax; r.y = ay; r.z = az; r.w = 0.f;
        all[(size_t)kdst * NN + gw] = r;
        float dv = -nd;
        g_tx1h[(size_t)kdst * NNP + gw] = pack4h(dv * ax, dv * ay, dv * az, 0.f);
    }
}

// out[i][c] = silu( b1[c] + sum_{k,f} TxAll[k][i][f] * W1[k][f][c] )
__global__ void k_l1_gemm(const float* __restrict__ W1, const float* __restrict__ b1,
                          int outsel) {
    __shared__ float Ws[24 * 96];
    for (int t = threadIdx.x; t < 24 * 96; t += blockDim.x) Ws[t] = W1[t];
    __syncthreads();
    int gw   = (blockIdx.x * blockDim.x + threadIdx.x) >> 5;
    int lane = threadIdx.x & 31;
    if (gw >= NN) return;
    const float4* all = (const float4*)g_tx1all;
    float acc = b1[lane];
#pragma unroll
    for (int k = 0; k < 24; k++) {
        float4 t = all[(size_t)k * NN + gw];
        acc = fmaf(t.x, Ws[k * 96 + 0  + lane], acc);
        acc = fmaf(t.y, Ws[k * 96 + 32 + lane], acc);
        acc = fmaf(t.z, Ws[k * 96 + 64 + lane], acc);
    }
    float r = silu(acc);
    selbuf(outsel)[gw * 32 + lane] = r;
    sel16(outsel)[gw * 32 + lane] = __float2half(g_dinv[gw] * r);
}

// ---------------- F=32 layers ------------------------------------------------
// maskless vectorized quad gather: padded rows (multiple of 16 edges), cols
// fetched as one int4 per lane per chunk; sentinel col NN has a zero row.
__device__ __forceinline__ void gatherquad4(const uint2* __restrict__ v4,
                                            int s, int e, int lane,
                                            float& a0, float& a1, float& a2, float& a3) {
    int eslot = lane >> 3;
    int q     = lane & 7;
    a0 = 0.f; a1 = 0.f; a2 = 0.f; a3 = 0.f;
    for (int base = s; base < e; base += 16) {
        int4 cc = __ldg(&g_ccsr4[(base >> 2) + eslot]);   // 4 consecutive cols
        uint2 h0 = __ldg(&v4[cc.x * 8 + q]);
        uint2 h1 = __ldg(&v4[cc.y * 8 + q]);
        uint2 h2 = __ldg(&v4[cc.z * 8 + q]);
        uint2 h3 = __ldg(&v4[cc.w * 8 + q]);
        float2 p, r;
        p = __half22float2(*reinterpret_cast<__half2*>(&h0.x));
        r = __half22float2(*reinterpret_cast<__half2*>(&h0.y));
        a0 += p.x; a1 += p.y; a2 += r.x; a3 += r.y;
        p = __half22float2(*reinterpret_cast<__half2*>(&h1.x));
        r = __half22float2(*reinterpret_cast<__half2*>(&h1.y));
        a0 += p.x; a1 += p.y; a2 += r.x; a3 += r.y;
        p = __half22float2(*reinterpret_cast<__half2*>(&h2.x));
        r = __half22float2(*reinterpret_cast<__half2*>(&h2.y));
        a0 += p.x; a1 += p.y; a2 += r.x; a3 += r.y;
        p = __half22float2(*reinterpret_cast<__half2*>(&h3.x));
        r = __half22float2(*reinterpret_cast<__half2*>(&h3.y));
        a0 += p.x; a1 += p.y; a2 += r.x; a3 += r.y;
    }
    // reduce across the 4 edge slots
    a0 += __shfl_xor_sync(FULLMASK, a0, 8);
    a1 += __shfl_xor_sync(FULLMASK, a1, 8);
    a2 += __shfl_xor_sync(FULLMASK, a2, 8);
    a3 += __shfl_xor_sync(FULLMASK, a3, 8);
    a0 += __shfl_xor_sync(FULLMASK, a0, 16);
    a1 += __shfl_xor_sync(FULLMASK, a1, 16);
    a2 += __shfl_xor_sync(FULLMASK, a2, 16);
    a3 += __shfl_xor_sync(FULLMASK, a3, 16);
}

// pure recurrence SpMV step: Tx = L(v) (tx0 == null) or 2 L(v) - tx0.
__global__ void k_spmv32(int vmirsel, const float* __restrict__ tx0,
                         float* __restrict__ dst, int dstmirsel) {
    int gw   = (blockIdx.x * blockDim.x + threadIdx.x) >> 5;
    int lane = threadIdx.x & 31;
    if (gw >= NN) return;
    float a0, a1, a2, a3;
    gatherquad4((const uint2*)sel16(vmirsel),
                g_indptr[gw], g_indptr[gw + 1], lane, a0, a1, a2, a3);
    if (lane < 8) {
        int q = lane;
        float dv = g_dinv[gw];
        float t0x = 0.f, t0y = 0.f, t0z = 0.f, t0w = 0.f;
        float sc = -dv;
        if (tx0 != nullptr) {
            float4 t0 = __ldg(&((const float4*)tx0)[(size_t)gw * 8 + q]);
            t0x = t0.x; t0y = t0.y; t0z = t0.z; t0w = t0.w;
            sc = -2.f * dv;
        }
        float4 r;
        r.x = fmaf(sc, a0, -t0x);
        r.y = fmaf(sc, a1, -t0y);
        r.z = fmaf(sc, a2, -t0z);
        r.w = fmaf(sc, a3, -t0w);
        ((float4*)dst)[(size_t)gw * 8 + q] = r;
        if (dstmirsel >= 0) {
            ((uint2*)sel16(dstmirsel))[(size_t)gw * 8 + q] =
                pack4h(dv * r.x, dv * r.y, dv * r.z, dv * r.w);
        }
    }
}

// per-layer epilogue GEMM: o = b + sum_{k=0..K-1} Tx_k @ W_k, Tx_0 = h.
// normal: out = silu(o) (+mirror). dofinal: dout[i] = sum_f silu(o)[f]*W4[f].
__global__ void k_epilogue(const float* __restrict__ W, const float* __restrict__ bias,
                           int K, int hsel, int outsel, int domirror,
                           const float* __restrict__ W4, float* __restrict__ dout) {
    __shared__ float4 sTx[2048];   // 256 nodes x 8 f4 = 32KB
    __shared__ float4 sW[256];     // 1024 floats = 4KB
    int t    = threadIdx.x;
    int n0   = blockIdx.x * 256;
    int lane = t & 31;
    int w    = t >> 5;
    int q    = lane & 7;   // out-quad (outs 4q..4q+3)
    int s    = lane >> 3;  // node sub-group
    float4 bq = ((const float4*)bias)[q];
    float4 acc[8];
#pragma unroll
    for (int i = 0; i < 8; i++) acc[i] = bq;
    for (int k = 0; k < K; k++) {
        const float4* src = (k == 0) ? (const float4*)selbuf(hsel)
                                     : (const float4*)(g_txs + (size_t)(k - 1) * NN * FC);
        __syncthreads();
        sW[t] = ((const float4*)(W + (size_t)k * 1024))[t];
#pragma unroll
        for (int r8 = 0; r8 < 8; r8++) {
            int idx  = r8 * 256 + t;
            int node = n0 + (idx >> 3);
            sTx[idx] = (node < NN) ? src[(size_t)n0 * 8 + idx]
                                   : make_float4(0.f, 0.f, 0.f, 0.f);
        }
        __syncthreads();
        int nbase = (w << 5) + (s << 3);
#pragma unroll
        for (int fq = 0; fq < 8; fq++) {
            float4 w0 = sW[(4 * fq + 0) * 8 + q];
            float4 w1 = sW[(4 * fq + 1) * 8 + q];
            float4 w2 = sW[(4 * fq + 2) * 8 + q];
            float4 w3 = sW[(4 * fq + 3) * 8 + q];
#pragma unroll
            for (int i = 0; i < 8; i++) {
                float4 a = sTx[(nbase + i) * 8 + fq];
                acc[i].x += a.x * w0.x + a.y * w1.x + a.z * w2.x + a.w * w3.x;
                acc[i].y += a.x * w0.y + a.y * w1.y + a.z * w2.y + a.w * w3.y;
                acc[i].z += a.x * w0.z + a.y * w1.z + a.z * w2.z + a.w * w3.z;
                acc[i].w += a.x * w0.w + a.y * w1.w + a.z * w2.w + a.w * w3.w;
            }
        }
    }
    int nbase = (w << 5) + (s << 3);
    if (dout != nullptr) {
        // fused final layer: p_i = dot(silu(o_i), W4); reduce over q lanes
        float4 w4q = ((const float4*)W4)[q];
        float p[8];
#pragma unroll
        for (int i = 0; i < 8; i++) {
            p[i] = silu(acc[i].x) * w4q.x + silu(acc[i].y) * w4q.y
                 + silu(acc[i].z) * w4q.z + silu(acc[i].w) * w4q.w;
        }
#pragma unroll
        for (int off = 1; off <= 4; off <<= 1) {
#pragma unroll
            for (int i = 0; i < 8; i++)
                p[i] += __shfl_xor_sync(FULLMASK, p[i], off);
        }
        if (q == 0) {
#pragma unroll
            for (int i = 0; i < 8; i++) {
                int node = n0 + nbase + i;
                if (node < NN) dout[node] = p[i];
            }
        }
        return;
    }
    float*  outp = selbuf(outsel);
    __half* mir  = sel16(outsel);
#pragma unroll
    for (int i = 0; i < 8; i++) {
        int node = n0 + nbase + i;
        if (node < NN) {
            float4 o;
            o.x = silu(acc[i].x);
            o.y = silu(acc[i].y);
            o.z = silu(acc[i].z);
            o.w = silu(acc[i].w);
            ((float4*)outp)[node * 8 + q] = o;
            if (domirror) {
                float dv = g_dinv[node];
                ((uint2*)mir)[node * 8 + q] =
                    pack4h(dv * o.x, dv * o.y, dv * o.z, dv * o.w);
            }
        }
    }
}

// ---------------- host orchestration ----------------------------------------
extern "C" void kernel_launch(void* const* d_in, const int* in_sizes, int n_in,
                              void* d_out, int out_size) {
    const float* x  = (const float*)d_in[0];
    const void*  ei = d_in[1];
    const float* W1 = (const float*)d_in[4];
    const float* b1 = (const float*)d_in[5];
    const float* W2 = (const float*)d_in[6];
    const float* b2 = (const float*)d_in[7];
    const float* W3 = (const float*)d_in[8];
    const float* b3 = (const float*)d_in[9];
    const float* W4 = (const float*)d_in[10];
    float* out = (float*)d_out;

    const int blocksN    = (NN + 255) / 256;
    const int blocksE    = (EE + 255) / 256;
    const int blocksScan = (NN + 511) / 512;
    const int blocksWarp = (NN * 32 + 255) / 256;
    const int blocksEpi  = (NN + 255) / 256;

    // resolve device-global addresses once (uncaptured correctness run)
    static float* txsbase = nullptr;
    static float* bufA    = nullptr;
    static float* bufB    = nullptr;
    if (txsbase == nullptr) {
        cudaGetSymbolAddress((void**)&txsbase, g_txs);
        cudaGetSymbolAddress((void**)&bufA, g_bufA);
        cudaGetSymbolAddress((void**)&bufB, g_bufB);
    }

    // --- dtype probe + CSR build ---
    k_init<<<blocksN, 256>>>((const int*)ei);
    k_edges<<<blocksE, 256>>>(ei);
    k_scan1<<<blocksScan, 512>>>();
    k_scan2<<<1, 512>>>(blocksScan);
    k_scan3<<<blocksN, 256>>>();
    k_fillpad<<<blocksE + blocksN, 256>>>(ei, x, blocksE);

    // --- layer 1: K=24, 3 -> 32, silu ---
    k_l1_spmv<<<blocksWarp, 256>>>(0, 1, -1);
    for (int k = 2; k < 24; k++)
        k_l1_spmv<<<blocksWarp, 256>>>(k - 1, k, k - 2);
    k_l1_gemm<<<blocksWarp, 256>>>(W1, b1, /*outsel=*/0);   // h1 -> bufA (+mirror A)

    // --- layer 2: K=12, h = bufA(0) -> out bufB(1) ---
    {
        const int K = 12;
        k_spmv32<<<blocksWarp, 256>>>(0, nullptr, txsbase, 2);     // Tx1 -> slot0, mir 2
        for (int k = 2; k < K; k++) {
            const float* tx0 = (k == 2) ? bufA
                                        : txsbase + (size_t)(k - 3) * NN * FC;
            float* dst = txsbase + (size_t)(k - 1) * NN * FC;
            int vmir   = (k & 1) ? 3 : 2;
            int dmir   = (k == K - 1) ? -1 : ((k & 1) ? 2 : 3);
            k_spmv32<<<blocksWarp, 256>>>(vmir, tx0, dst, dmir);
        }
        k_epilogue<<<blocksEpi, 256>>>(W2, b2, K, 0, 1, 1, nullptr, nullptr);
    }

    // --- layer 3: K=10, h = bufB(1); epilogue fused with final W4 projection ---
    {
        const int K = 10;
        k_spmv32<<<blocksWarp, 256>>>(1, nullptr, txsbase, 2);     // Tx1 -> slot0, mir 2
        for (int k = 2; k < K; k++) {
            const float* tx0 = (k == 2) ? bufB
                                        : txsbase + (size_t)(k - 3) * NN * FC;
            float* dst = txsbase + (size_t)(k - 1) * NN * FC;
            int vmir   = (k & 1) ? 3 : 2;
            int dmir   = (k == K - 1) ? -1 : ((k & 1) ? 2 : 3);
            k_spmv32<<<blocksWarp, 256>>>(vmir, tx0, dst, dmir);
        }
        k_epilogue<<<blocksEpi, 256>>>(W3, b3, K, 1, 0, 0, W4, out);
    }

    (void)in_sizes; (void)n_in; (void)out_size;
}

// round 16
// speedup vs baseline: 1.0287x; 1.0287x over previous
#include <cuda_runtime.h>
#include <cuda_fp16.h>
#include <cstdint>

#define NN 100000
#define EE 3200000
#define FC 32
#define FULLMASK 0xFFFFFFFFu

// ---------------- scratch (device globals; no allocation anywhere) ----------
__device__ int   g_is64;
__device__ int   g_deg[NN];
__device__ float g_dinv[NN];
__device__ int   g_indptr[NN + 1];
__device__ int   g_pos[NN];
__device__ int   g_ccsr[EE];          // column indices only (dinv folded into mirrors)
__device__ int   g_partials[512];

__device__ float g_tx1all[24 * NN * 4];   // layer1 basis fp32, float4-padded
__device__ uint2 g_tx1h[24 * NN];         // layer1 fp16x4 mirror, PRE-SCALED by dinv
__device__ float g_txs[11 * NN * FC + 8192];  // Tx_1..Tx_11 fp32
__device__ float  g_bufA[NN * FC + 8192];
__device__ float  g_bufB[NN * FC + 8192];
__device__ __half g_h16A[NN * FC];        // fp16 mirrors, PRE-SCALED by dinv
__device__ __half g_h16B[NN * FC];
__device__ __half g_h16C[NN * FC];
__device__ __half g_h16D[NN * FC];

__device__ __forceinline__ float* selbuf(int s) {
    return (s == 0) ? g_bufA : g_bufB;
}
__device__ __forceinline__ __half* sel16(int s) {
    switch (s) {
        case 0:  return g_h16A;
        case 1:  return g_h16B;
        case 2:  return g_h16C;
        default: return g_h16D;
    }
}

__device__ __forceinline__ float silu(float x) {
    return x / (1.f + __expf(-x));
}

__device__ __forceinline__ uint2 pack4h(float a, float b, float c, float d) {
    __half2 lo = __floats2half2_rn(a, b);
    __half2 hi = __floats2half2_rn(c, d);
    uint2 r;
    r.x = *reinterpret_cast<unsigned*>(&lo);
    r.y = *reinterpret_cast<unsigned*>(&hi);
    return r;
}

// ---------------- dtype detect + zero degrees (merged) -----------------------
__global__ void k_init(const int* __restrict__ ei32) {
    int i = blockIdx.x * blockDim.x + threadIdx.x;
    if (i < NN) g_deg[i] = 0;
    if (blockIdx.x == 0) {
        __shared__ int ok;
        if (threadIdx.x == 0) ok = 1;
        __syncthreads();
        if (ei32[2 * threadIdx.x + 1] != 0) ok = 0;
        __syncthreads();
        if (threadIdx.x == 0) g_is64 = ok;
    }
}

// ---------------- graph preprocessing ---------------------------------------
__device__ __forceinline__ void decode_edge(const void* eiv, int e, int& r, int& c) {
    if (g_is64) {
        const long long* ei = (const long long*)eiv;
        r = (int)ei[e];
        c = (int)ei[EE + e];
    } else {
        const int* ei = (const int*)eiv;
        r = ei[e];
        c = ei[EE + e];
    }
    if ((unsigned)r >= NN) r = 0;
    if ((unsigned)c >= NN) c = 0;
}

__global__ void k_edges(const void* __restrict__ eiv) {
    int e = blockIdx.x * blockDim.x + threadIdx.x;
    if (e >= EE) return;
    int r, c;
    decode_edge(eiv, e, r, c);
    if (r != c) atomicAdd(&g_deg[r], 1);
}

// chunked exclusive scan of g_deg into g_indptr (chunk = 512)
__global__ void k_scan1() {
    __shared__ int s[512];
    int i = blockIdx.x * 512 + threadIdx.x;
    int v = (i < NN) ? g_deg[i] : 0;
    s[threadIdx.x] = v;
    __syncthreads();
    for (int off = 1; off < 512; off <<= 1) {
        int t = 0;
        if (threadIdx.x >= off) t = s[threadIdx.x - off];
        __syncthreads();
        if (threadIdx.x >= off) s[threadIdx.x] += t;
        __syncthreads();
    }
    if (i < NN) g_indptr[i] = s[threadIdx.x] - v;
    if (threadIdx.x == 511) g_partials[blockIdx.x] = s[511];
}

__global__ void k_scan2(int nb) {
    __shared__ int s[512];
    int v = (threadIdx.x < nb) ? g_partials[threadIdx.x] : 0;
    s[threadIdx.x] = v;
    __syncthreads();
    for (int off = 1; off < 512; off <<= 1) {
        int t = 0;
        if (threadIdx.x >= off) t = s[threadIdx.x - off];
        __syncthreads();
        if (threadIdx.x >= off) s[threadIdx.x] += t;
        __syncthreads();
    }
    if (threadIdx.x < nb) g_partials[threadIdx.x] = s[threadIdx.x] - v;
    if (threadIdx.x == 511) g_indptr[NN] = s[511];
}

// scan finalize + dinv (merged)
__global__ void k_scan3() {
    int i = blockIdx.x * blockDim.x + threadIdx.x;
    if (i < NN) {
        int p = g_indptr[i] + g_partials[i >> 9];
        g_indptr[i] = p;
        g_pos[i] = p;
        int d = g_deg[i];
        g_dinv[i] = (d > 0) ? rsqrtf((float)d) : 0.f;
    }
}

// fill CSR (cols only, re-decoding ei) + pad x into layer-1 slot 0
__global__ void k_fillpad(const void* __restrict__ eiv, const float* __restrict__ x,
                          int blocksE) {
    if ((int)blockIdx.x < blocksE) {
        int e = blockIdx.x * blockDim.x + threadIdx.x;
        if (e >= EE) return;
        int r, c;
        decode_edge(eiv, e, r, c);
        if (r != c) {
            int p = atomicAdd(&g_pos[r], 1);
            g_ccsr[p] = c;
        }
    } else {
        int i = (blockIdx.x - blocksE) * blockDim.x + threadIdx.x;
        if (i >= NN) return;
        float a = x[3 * i + 0];
        float b = x[3 * i + 1];
        float c = x[3 * i + 2];
        float4 t; t.x = a; t.y = b; t.z = c; t.w = 0.f;
        ((float4*)g_tx1all)[i] = t;
        float dv = g_dinv[i];
        g_tx1h[i] = pack4h(dv * a, dv * b, dv * c, 0.f);
    }
}

// ---------------- layer 1 (F=3, fp16x4 scaled gather), warp per node --------
__global__ void k_l1_spmv(int ksrc, int kdst, int ktx0) {
    int gw   = (blockIdx.x * blockDim.x + threadIdx.x) >> 5;
    int lane = threadIdx.x & 31;
    if (gw >= NN) return;
    const uint2* vh = g_tx1h + (size_t)ksrc * NN;
    int s = g_indptr[gw];
    int e = g_indptr[gw + 1];
    float ax = 0.f, ay = 0.f, az = 0.f;
    for (int base = s; base < e; base += 32) {
        int j = base + lane;
        if (j < e) {
            int c = __ldg(&g_ccsr[j]);
            uint2 hv = __ldg(&vh[c]);
            float2 f01 = __half22float2(*reinterpret_cast<__half2*>(&hv.x));
            float2 f23 = __half22float2(*reinterpret_cast<__half2*>(&hv.y));
            ax += f01.x;
            ay += f01.y;
            az += f23.x;
        }
    }
#pragma unroll
    for (int off = 16; off; off >>= 1) {
        ax += __shfl_xor_sync(FULLMASK, ax, off);
        ay += __shfl_xor_sync(FULLMASK, ay, off);
        az += __shfl_xor_sync(FULLMASK, az, off);
    }
    if (lane == 0) {
        float nd = -g_dinv[gw];          // L = -dinv[r] * sum(scaled mirror)
        ax *= nd; ay *= nd; az *= nd;
        float4* all = (float4*)g_tx1all;
        if (ktx0 >= 0) {
            float4 t0 = all[(size_t)ktx0 * NN + gw];
            ax = 2.f * ax - t0.x;
            ay = 2.f * ay - t0.y;
            az = 2.f * az - t0.z;
        }
        float4 r; r.x = ax; r.y = ay; r.z = az; r.w = 0.f;
        all[(size_t)kdst * NN + gw] = r;
        float dv = -nd;
        g_tx1h[(size_t)kdst * NN + gw] = pack4h(dv * ax, dv * ay, dv * az, 0.f);
    }
}

// fused last layer-1 step (k=23) + GEMM:
// slot23 = 2 L(slot22) - slot21 (kept in registers, never stored);
// out[i][c] = silu(b1[c] + sum_{k=0..22} slotk[i]·W1[k][:][c] + slot23[i]·W1[23][:][c])
__global__ void k_l1_last(const float* __restrict__ W1, const float* __restrict__ b1,
                          int outsel) {
    __shared__ float Ws[24 * 96];
    for (int t = threadIdx.x; t < 24 * 96; t += blockDim.x) Ws[t] = W1[t];
    __syncthreads();
    int gw   = (blockIdx.x * blockDim.x + threadIdx.x) >> 5;
    int lane = threadIdx.x & 31;
    if (gw >= NN) return;
    const uint2* vh = g_tx1h + (size_t)22 * NN;
    int s = g_indptr[gw];
    int e = g_indptr[gw + 1];
    float ax = 0.f, ay = 0.f, az = 0.f;
    for (int base = s; base < e; base += 32) {
        int j = base + lane;
        if (j < e) {
            int c = __ldg(&g_ccsr[j]);
            uint2 hv = __ldg(&vh[c]);
            float2 f01 = __half22float2(*reinterpret_cast<__half2*>(&hv.x));
            float2 f23 = __half22float2(*reinterpret_cast<__half2*>(&hv.y));
            ax += f01.x;
            ay += f01.y;
            az += f23.x;
        }
    }
#pragma unroll
    for (int off = 16; off; off >>= 1) {
        ax += __shfl_xor_sync(FULLMASK, ax, off);
        ay += __shfl_xor_sync(FULLMASK, ay, off);
        az += __shfl_xor_sync(FULLMASK, az, off);
    }
    const float4* all = (const float4*)g_tx1all;
    // lane 0 finishes the recurrence; broadcast slot23 to all lanes
    if (lane == 0) {
        float nd = -g_dinv[gw];
        ax *= nd; ay *= nd; az *= nd;
        float4 t0 = all[(size_t)21 * NN + gw];
        ax = 2.f * ax - t0.x;
        ay = 2.f * ay - t0.y;
        az = 2.f * az - t0.z;
    }
    ax = __shfl_sync(FULLMASK, ax, 0);
    ay = __shfl_sync(FULLMASK, ay, 0);
    az = __shfl_sync(FULLMASK, az, 0);
    float acc = b1[lane];
#pragma unroll
    for (int k = 0; k < 23; k++) {
        float4 t = all[(size_t)k * NN + gw];   // warp-uniform broadcast load
        acc = fmaf(t.x, Ws[k * 96 + 0  + lane], acc);
        acc = fmaf(t.y, Ws[k * 96 + 32 + lane], acc);
        acc = fmaf(t.z, Ws[k * 96 + 64 + lane], acc);
    }
    acc = fmaf(ax, Ws[23 * 96 + 0  + lane], acc);
    acc = fmaf(ay, Ws[23 * 96 + 32 + lane], acc);
    acc = fmaf(az, Ws[23 * 96 + 64 + lane], acc);
    float r = silu(acc);
    selbuf(outsel)[gw * 32 + lane] = r;
    sel16(outsel)[gw * 32 + lane] = __float2half(g_dinv[gw] * r);
}

// ---------------- F=32 layers ------------------------------------------------
// two-phase quad gather on pre-scaled mirrors (R12 version: masked, no padding).
__device__ __forceinline__ void gatherquad4(const uint2* __restrict__ v4,
                                            int s, int e, int lane,
                                            float& a0, float& a1, float& a2, float& a3) {
    int eslot = lane >> 3;
    int q     = lane & 7;
    a0 = 0.f; a1 = 0.f; a2 = 0.f; a3 = 0.f;
    for (int base = s; base < e; base += 16) {
        int  c[4];
        bool m[4];
#pragma unroll
        for (int t = 0; t < 4; t++) {
            int j = base + 4 * t + eslot;
            m[t] = (j < e);
            c[t] = m[t] ? __ldg(&g_ccsr[j]) : 0;
        }
#pragma unroll
        for (int t = 0; t < 4; t++) {
            if (m[t]) {
                uint2 hv = __ldg(&v4[c[t] * 8 + q]);
                float2 f01 = __half22float2(*reinterpret_cast<__half2*>(&hv.x));
                float2 f23 = __half22float2(*reinterpret_cast<__half2*>(&hv.y));
                a0 += f01.x;
                a1 += f01.y;
                a2 += f23.x;
                a3 += f23.y;
            }
        }
    }
    // reduce across the 4 edge slots
    a0 += __shfl_xor_sync(FULLMASK, a0, 8);
    a1 += __shfl_xor_sync(FULLMASK, a1, 8);
    a2 += __shfl_xor_sync(FULLMASK, a2, 8);
    a3 += __shfl_xor_sync(FULLMASK, a3, 8);
    a0 += __shfl_xor_sync(FULLMASK, a0, 16);
    a1 += __shfl_xor_sync(FULLMASK, a1, 16);
    a2 += __shfl_xor_sync(FULLMASK, a2, 16);
    a3 += __shfl_xor_sync(FULLMASK, a3, 16);
}

// pure recurrence SpMV step: Tx = L(v) (tx0 == null) or 2 L(v) - tx0.
__global__ void k_spmv32(int vmirsel, const float* __restrict__ tx0,
                         float* __restrict__ dst, int dstmirsel) {
    int gw   = (blockIdx.x * blockDim.x + threadIdx.x) >> 5;
    int lane = threadIdx.x & 31;
    if (gw >= NN) return;
    float a0, a1, a2, a3;
    gatherquad4((const uint2*)sel16(vmirsel),
                g_indptr[gw], g_indptr[gw + 1], lane, a0, a1, a2, a3);
    if (lane < 8) {
        int q = lane;
        float dv = g_dinv[gw];
        float t0x = 0.f, t0y = 0.f, t0z = 0.f, t0w = 0.f;
        float sc = -dv;
        if (tx0 != nullptr) {
            float4 t0 = __ldg(&((const float4*)tx0)[(size_t)gw * 8 + q]);
            t0x = t0.x; t0y = t0.y; t0z = t0.z; t0w = t0.w;
            sc = -2.f * dv;
        }
        float4 r;
        r.x = fmaf(sc, a0, -t0x);
        r.y = fmaf(sc, a1, -t0y);
        r.z = fmaf(sc, a2, -t0z);
        r.w = fmaf(sc, a3, -t0w);
        ((float4*)dst)[(size_t)gw * 8 + q] = r;
        if (dstmirsel >= 0) {
            ((uint2*)sel16(dstmirsel))[(size_t)gw * 8 + q] =
                pack4h(dv * r.x, dv * r.y, dv * r.z, dv * r.w);
        }
    }
}

// per-layer epilogue GEMM: o = b + sum_{k=0..K-1} Tx_k @ W_k, Tx_0 = h.
// normal: out = silu(o) (+mirror). dofinal: dout[i] = sum_f silu(o)[f]*W4[f].
__global__ void k_epilogue(const float* __restrict__ W, const float* __restrict__ bias,
                           int K, int hsel, int outsel, int domirror,
                           const float* __restrict__ W4, float* __restrict__ dout) {
    __shared__ float4 sTx[2048];   // 256 nodes x 8 f4 = 32KB
    __shared__ float4 sW[256];     // 1024 floats = 4KB
    int t    = threadIdx.x;
    int n0   = blockIdx.x * 256;
    int lane = t & 31;
    int w    = t >> 5;
    int q    = lane & 7;   // out-quad (outs 4q..4q+3)
    int s    = lane >> 3;  // node sub-group
    float4 bq = ((const float4*)bias)[q];
    float4 acc[8];
#pragma unroll
    for (int i = 0; i < 8; i++) acc[i] = bq;
    for (int k = 0; k < K; k++) {
        const float4* src = (k == 0) ? (const float4*)selbuf(hsel)
                                     : (const float4*)(g_txs + (size_t)(k - 1) * NN * FC);
        __syncthreads();
        sW[t] = ((const float4*)(W + (size_t)k * 1024))[t];
#pragma unroll
        for (int r8 = 0; r8 < 8; r8++) {
            int idx  = r8 * 256 + t;
            int node = n0 + (idx >> 3);
            sTx[idx] = (node < NN) ? src[(size_t)n0 * 8 + idx]
                                   : make_float4(0.f, 0.f, 0.f, 0.f);
        }
        __syncthreads();
        int nbase = (w << 5) + (s << 3);
#pragma unroll
        for (int fq = 0; fq < 8; fq++) {
            float4 w0 = sW[(4 * fq + 0) * 8 + q];
            float4 w1 = sW[(4 * fq + 1) * 8 + q];
            float4 w2 = sW[(4 * fq + 2) * 8 + q];
            float4 w3 = sW[(4 * fq + 3) * 8 + q];
#pragma unroll
            for (int i = 0; i < 8; i++) {
                float4 a = sTx[(nbase + i) * 8 + fq];
                acc[i].x += a.x * w0.x + a.y * w1.x + a.z * w2.x + a.w * w3.x;
                acc[i].y += a.x * w0.y + a.y * w1.y + a.z * w2.y + a.w * w3.y;
                acc[i].z += a.x * w0.z + a.y * w1.z + a.z * w2.z + a.w * w3.z;
                acc[i].w += a.x * w0.w + a.y * w1.w + a.z * w2.w + a.w * w3.w;
            }
        }
    }
    int nbase = (w << 5) + (s << 3);
    if (dout != nullptr) {
        // fused final layer: p_i = dot(silu(o_i), W4); reduce over q lanes
        float4 w4q = ((const float4*)W4)[q];
        float p[8];
#pragma unroll
        for (int i = 0; i < 8; i++) {
            p[i] = silu(acc[i].x) * w4q.x + silu(acc[i].y) * w4q.y
                 + silu(acc[i].z) * w4q.z + silu(acc[i].w) * w4q.w;
        }
#pragma unroll
        for (int off = 1; off <= 4; off <<= 1) {
#pragma unroll
            for (int i = 0; i < 8; i++)
                p[i] += __shfl_xor_sync(FULLMASK, p[i], off);
        }
        if (q == 0) {
#pragma unroll
            for (int i = 0; i < 8; i++) {
                int node = n0 + nbase + i;
                if (node < NN) dout[node] = p[i];
            }
        }
        return;
    }
    float*  outp = selbuf(outsel);
    __half* mir  = sel16(outsel);
#pragma unroll
    for (int i = 0; i < 8; i++) {
        int node = n0 + nbase + i;
        if (node < NN) {
            float4 o;
            o.x = silu(acc[i].x);
            o.y = silu(acc[i].y);
            o.z = silu(acc[i].z);
            o.w = silu(acc[i].w);
            ((float4*)outp)[node * 8 + q] = o;
            if (domirror) {
                float dv = g_dinv[node];
                ((uint2*)mir)[node * 8 + q] =
                    pack4h(dv * o.x, dv * o.y, dv * o.z, dv * o.w);
            }
        }
    }
}

// ---------------- host orchestration ----------------------------------------
extern "C" void kernel_launch(void* const* d_in, const int* in_sizes, int n_in,
                              void* d_out, int out_size) {
    const float* x  = (const float*)d_in[0];
    const void*  ei = d_in[1];
    const float* W1 = (const float*)d_in[4];
    const float* b1 = (const float*)d_in[5];
    const float* W2 = (const float*)d_in[6];
    const float* b2 = (const float*)d_in[7];
    const float* W3 = (const float*)d_in[8];
    const float* b3 = (const float*)d_in[9];
    const float* W4 = (const float*)d_in[10];
    float* out = (float*)d_out;

    const int blocksN    = (NN + 255) / 256;
    const int blocksE    = (EE + 255) / 256;
    const int blocksScan = (NN + 511) / 512;
    const int blocksWarp = (NN * 32 + 255) / 256;
    const int blocksEpi  = (NN + 255) / 256;

    // resolve device-global addresses once (uncaptured correctness run)
    static float* txsbase = nullptr;
    static float* bufA    = nullptr;
    static float* bufB    = nullptr;
    if (txsbase == nullptr) {
        cudaGetSymbolAddress((void**)&txsbase, g_txs);
        cudaGetSymbolAddress((void**)&bufA, g_bufA);
        cudaGetSymbolAddress((void**)&bufB, g_bufB);
    }

    // --- dtype probe + CSR build ---
    k_init<<<blocksN, 256>>>((const int*)ei);
    k_edges<<<blocksE, 256>>>(ei);
    k_scan1<<<blocksScan, 512>>>();
    k_scan2<<<1, 512>>>(blocksScan);
    k_scan3<<<blocksN, 256>>>();
    k_fillpad<<<blocksE + blocksN, 256>>>(ei, x, blocksE);

    // --- layer 1: K=24, 3 -> 32, silu; last step fused with GEMM ---
    k_l1_spmv<<<blocksWarp, 256>>>(0, 1, -1);
    for (int k = 2; k < 23; k++)
        k_l1_spmv<<<blocksWarp, 256>>>(k - 1, k, k - 2);
    k_l1_last<<<blocksWarp, 256>>>(W1, b1, /*outsel=*/0);   // h1 -> bufA (+mirror A)

    // --- layer 2: K=12, h = bufA(0) -> out bufB(1) ---
    {
        const int K = 12;
        k_spmv32<<<blocksWarp, 256>>>(0, nullptr, txsbase, 2);     // Tx1 -> slot0, mir 2
        for (int k = 2; k < K; k++) {
            const float* tx0 = (k == 2) ? bufA
                                        : txsbase + (size_t)(k - 3) * NN * FC;
            float* dst = txsbase + (size_t)(k - 1) * NN * FC;
            int vmir   = (k & 1) ? 3 : 2;
            int dmir   = (k == K - 1) ? -1 : ((k & 1) ? 2 : 3);
            k_spmv32<<<blocksWarp, 256>>>(vmir, tx0, dst, dmir);
        }
        k_epilogue<<<blocksEpi, 256>>>(W2, b2, K, 0, 1, 1, nullptr, nullptr);
    }

    // --- layer 3: K=10, h = bufB(1); epilogue fused with final W4 projection ---
    {
        const int K = 10;
        k_spmv32<<<blocksWarp, 256>>>(1, nullptr, txsbase, 2);     // Tx1 -> slot0, mir 2
        for (int k = 2; k < K; k++) {
            const float* tx0 = (k == 2) ? bufB
                                        : txsbase + (size_t)(k - 3) * NN * FC;
            float* dst = txsbase + (size_t)(k - 1) * NN * FC;
            int vmir   = (k & 1) ? 3 : 2;
            int dmir   = (k == K - 1) ? -1 : ((k & 1) ? 2 : 3);
            k_spmv32<<<blocksWarp, 256>>>(vmir, tx0, dst, dmir);
        }
        k_epilogue<<<blocksEpi, 256>>>(W3, b3, K, 1, 0, 0, W4, out);
    }

    (void)in_sizes; (void)n_in; (void)out_size;
}